// round 2
// baseline (speedup 1.0000x reference)
#include <cuda_runtime.h>
#include <cuda_fp16.h>
#include <cstdint>
#include <cstddef>

// ---------------------------------------------------------------------------
// Problem constants
// ---------------------------------------------------------------------------
#define DIM   4096
#define HID   11008
#define MTOK  4096          // B*S = 2*2048

static constexpr int BM = 128;
static constexpr int BN = 256;
static constexpr int BK = 64;          // 64 fp16 = 128 bytes per row (SW128 atom)
static constexpr int THREADS = 256;    // 8 warps, warp grid 2(m) x 4(n), warp tile 64x64
static constexpr int STAGES = 3;

static constexpr int A_BYTES = BM * 128;           // 16 KB
static constexpr int B_BYTES = BN * 128;           // 32 KB
static constexpr int STAGE_BYTES = A_BYTES + B_BYTES;   // 48 KB
static constexpr int SMEM_BYTES = STAGES * STAGE_BYTES; // 144 KB

// ---------------------------------------------------------------------------
// NF4 codebook
// ---------------------------------------------------------------------------
__constant__ float c_nf4[16] = {
    -1.0f, -0.6961928009986877f, -0.5250730514526367f, -0.39491748809814453f,
    -0.28444138169288635f, -0.18477343022823334f, -0.09105003625154495f, 0.0f,
    0.07958029955625534f, 0.16093020141124725f, 0.24611230194568634f,
    0.33791524171829224f, 0.44070982933044434f, 0.5626170039176941f,
    0.6989939212799072f, 1.0f};

// ---------------------------------------------------------------------------
// Static device scratch (no runtime allocation allowed)
// ---------------------------------------------------------------------------
__device__ __align__(256) __half g_w1[(size_t)HID * DIM];
__device__ __align__(256) __half g_w3[(size_t)HID * DIM];
__device__ __align__(256) __half g_w2[(size_t)DIM * HID];
__device__ __align__(256) __half g_x [(size_t)MTOK * DIM];
__device__ __align__(256) __half g_g1[(size_t)MTOK * HID];
__device__ __align__(256) __half g_g3[(size_t)MTOK * HID];
__device__ __align__(256) __half g_h [(size_t)MTOK * HID];

// ---------------------------------------------------------------------------
// PTX helpers (sm_100 baseline: cp.async, ldmatrix, mma.sync)
// ---------------------------------------------------------------------------
__device__ __forceinline__ uint32_t smem_u32(const void* p) {
    uint32_t r;
    asm("{ .reg .u64 t; cvta.to.shared.u64 t, %1; cvt.u32.u64 %0, t; }"
        : "=r"(r) : "l"(p));
    return r;
}

__device__ __forceinline__ void cp_async16(uint32_t dst, const void* src) {
    asm volatile("cp.async.cg.shared.global [%0], [%1], 16;" :: "r"(dst), "l"(src));
}
__device__ __forceinline__ void cp_async_commit() {
    asm volatile("cp.async.commit_group;" ::: "memory");
}
template <int N>
__device__ __forceinline__ void cp_async_wait() {
    asm volatile("cp.async.wait_group %0;" :: "n"(N) : "memory");
}

__device__ __forceinline__ void ldsm_x4(uint32_t* r, uint32_t addr) {
    asm volatile("ldmatrix.sync.aligned.m8n8.x4.shared.b16 {%0,%1,%2,%3}, [%4];"
                 : "=r"(r[0]), "=r"(r[1]), "=r"(r[2]), "=r"(r[3]) : "r"(addr));
}

__device__ __forceinline__ void mma16816(float* c, const uint32_t* a, const uint32_t* b) {
    asm volatile(
        "mma.sync.aligned.m16n8k16.row.col.f32.f16.f16.f32 "
        "{%0,%1,%2,%3}, {%4,%5,%6,%7}, {%8,%9}, {%0,%1,%2,%3};"
        : "+f"(c[0]), "+f"(c[1]), "+f"(c[2]), "+f"(c[3])
        : "r"(a[0]), "r"(a[1]), "r"(a[2]), "r"(a[3]), "r"(b[0]), "r"(b[1]));
}

// SW128 swizzle of a byte offset within a tile of 128-byte rows.
__device__ __forceinline__ uint32_t sw128(uint32_t off) {
    return off ^ ((off >> 3) & 0x70);
}

// Load a ROWS x 64(fp16) K-major tile into SW128-swizzled SMEM via cp.async.
template <int ROWS>
__device__ __forceinline__ void load_tile(const __half* __restrict__ g, int ldg,
                                          int row0, int k0, uint32_t sbase, int tid) {
    constexpr int CHUNKS = ROWS * 8;          // 16B chunks
    constexpr int ITER = CHUNKS / THREADS;
#pragma unroll
    for (int i = 0; i < ITER; ++i) {
        int c = tid + i * THREADS;
        int r = c >> 3, cc = c & 7;
        const __half* src = g + (size_t)(row0 + r) * ldg + k0 + cc * 8;
        cp_async16(sbase + sw128((uint32_t)(r * 128 + cc * 16)), src);
    }
}

// ---------------------------------------------------------------------------
// Dequant / convert / swiglu elementwise kernels
// ---------------------------------------------------------------------------
__global__ void __launch_bounds__(256)
dequant_nf4_kernel(const int* __restrict__ codes, const float* __restrict__ absmax,
                   __half* __restrict__ out, int total, int K) {
    int t = blockIdx.x * 256 + threadIdx.x;
    int base = t * 8;
    if (base >= total) return;
    int4 c0 = *reinterpret_cast<const int4*>(codes + base);
    int4 c1 = *reinterpret_cast<const int4*>(codes + base + 4);
    int row = base / K;
    int col = base - row * K;
    float am = absmax[row * (K >> 6) + (col >> 6)];
    __half2 hs[4];
    hs[0] = __floats2half2_rn(c_nf4[c0.x] * am, c_nf4[c0.y] * am);
    hs[1] = __floats2half2_rn(c_nf4[c0.z] * am, c_nf4[c0.w] * am);
    hs[2] = __floats2half2_rn(c_nf4[c1.x] * am, c_nf4[c1.y] * am);
    hs[3] = __floats2half2_rn(c_nf4[c1.z] * am, c_nf4[c1.w] * am);
    *reinterpret_cast<uint4*>(out + base) = *reinterpret_cast<const uint4*>(hs);
}

__global__ void __launch_bounds__(256)
convert_x_kernel(const float* __restrict__ x, __half* __restrict__ out, int total) {
    int t = blockIdx.x * 256 + threadIdx.x;
    int base = t * 8;
    if (base >= total) return;
    float4 a = reinterpret_cast<const float4*>(x + base)[0];
    float4 b = reinterpret_cast<const float4*>(x + base)[1];
    __half2 hs[4];
    hs[0] = __floats2half2_rn(a.x, a.y);
    hs[1] = __floats2half2_rn(a.z, a.w);
    hs[2] = __floats2half2_rn(b.x, b.y);
    hs[3] = __floats2half2_rn(b.z, b.w);
    *reinterpret_cast<uint4*>(out + base) = *reinterpret_cast<const uint4*>(hs);
}

__global__ void __launch_bounds__(256)
swiglu_kernel(const __half* __restrict__ g1, const __half* __restrict__ g3,
              __half* __restrict__ h, int total) {
    int t = blockIdx.x * 256 + threadIdx.x;
    int base = t * 8;
    if (base >= total) return;
    __half2 a[4], b[4], o[4];
    *reinterpret_cast<uint4*>(a) = *reinterpret_cast<const uint4*>(g1 + base);
    *reinterpret_cast<uint4*>(b) = *reinterpret_cast<const uint4*>(g3 + base);
#pragma unroll
    for (int i = 0; i < 4; ++i) {
        float2 fa = __half22float2(a[i]);
        float2 fb = __half22float2(b[i]);
        float h0 = (fa.x / (1.f + __expf(-fa.x))) * fb.x;
        float h1 = (fa.y / (1.f + __expf(-fa.y))) * fb.y;
        o[i] = __floats2half2_rn(h0, h1);
    }
    *reinterpret_cast<uint4*>(h + base) = *reinterpret_cast<const uint4*>(o);
}

// ---------------------------------------------------------------------------
// HMMA GEMM: C[M, N] = A[M, K] * B[N, K]^T   (both K-major), fp32 accumulate.
// CTA 128x256x64, 8 warps of 64x64, 3-stage cp.async pipeline, SW128 smem.
// Grouped raster: groups of G m-tiles sweep all n-tiles (L2 reuse).
// ---------------------------------------------------------------------------
template <typename OutT>
__global__ void __launch_bounds__(THREADS)
gemm_kernel(const __half* __restrict__ A, const __half* __restrict__ B,
            OutT* __restrict__ C, int TN, int K, int ldc) {
    extern __shared__ char smem[];
    const int tid = threadIdx.x;
    const int wid = tid >> 5, lane = tid & 31;
    const uint32_t sb = smem_u32(smem);

    // grouped raster
    const int G = 8;
    const int bid = blockIdx.x;
    const int group = bid / (G * TN);
    const int rem = bid - group * (G * TN);
    const int bm = group * G + (rem % G);
    const int bn = rem / G;
    const int row0 = bm * BM, col0 = bn * BN;

    const int wm = (wid & 1) * 64;       // warp m offset in tile
    const int wn = (wid >> 1) * 64;      // warp n offset in tile

    uint32_t sA[STAGES], sB[STAGES];
#pragma unroll
    for (int s = 0; s < STAGES; ++s) {
        sA[s] = sb + s * STAGE_BYTES;
        sB[s] = sA[s] + A_BYTES;
    }

    const int KT = K / BK;

    // prologue: stages 0 .. STAGES-2
#pragma unroll
    for (int s = 0; s < STAGES - 1; ++s) {
        load_tile<BM>(A, K, row0, s * BK, sA[s], tid);
        load_tile<BN>(B, K, col0, s * BK, sB[s], tid);
        cp_async_commit();
    }

    float acc[4][8][4];
#pragma unroll
    for (int i = 0; i < 4; ++i)
#pragma unroll
        for (int j = 0; j < 8; ++j)
#pragma unroll
            for (int q = 0; q < 4; ++q) acc[i][j][q] = 0.f;

    // per-thread ldmatrix address components
    const int a_row = wm + ((lane >> 3) & 1) * 8 + (lane & 7);   // + im*16
    const int a_kb  = ((lane >> 4) & 1) * 16;                    // + ks*32
    const int b_row = wn + ((lane >> 4) & 1) * 8 + (lane & 7);   // + j16*16
    const int b_kb  = ((lane >> 3) & 1) * 16;                    // + ks*32

    for (int kt = 0; kt < KT; ++kt) {
        {   // prefetch ktile kt+STAGES-1 (clamped; duplicates at tail are dead data)
            int kp = kt + STAGES - 1; if (kp >= KT) kp = KT - 1;
            const int sbuf = (kt + STAGES - 1) % STAGES;
            load_tile<BM>(A, K, row0, kp * BK, sA[sbuf], tid);
            load_tile<BN>(B, K, col0, kp * BK, sB[sbuf], tid);
            cp_async_commit();
        }
        cp_async_wait<STAGES - 1>();
        __syncthreads();

        const uint32_t aA = sA[kt % STAGES];
        const uint32_t aB = sB[kt % STAGES];
#pragma unroll
        for (int ks = 0; ks < 4; ++ks) {
            uint32_t af[4][4], bf[4][4];
#pragma unroll
            for (int im = 0; im < 4; ++im) {
                uint32_t off = (uint32_t)((a_row + im * 16) * 128 + ks * 32 + a_kb);
                ldsm_x4(af[im], aA + sw128(off));
            }
#pragma unroll
            for (int j16 = 0; j16 < 4; ++j16) {
                uint32_t off = (uint32_t)((b_row + j16 * 16) * 128 + ks * 32 + b_kb);
                ldsm_x4(bf[j16], aB + sw128(off));
            }
#pragma unroll
            for (int im = 0; im < 4; ++im)
#pragma unroll
                for (int j16 = 0; j16 < 4; ++j16) {
                    mma16816(acc[im][2 * j16],     af[im], &bf[j16][0]);
                    mma16816(acc[im][2 * j16 + 1], af[im], &bf[j16][2]);
                }
        }
        __syncthreads();
    }

    // epilogue: thread t owns (m = r + t/4 [+8], n = (t%4)*2 [, +1]) per 16x8 tile
    const int er = lane >> 2;
    const int ec = (lane & 3) * 2;
#pragma unroll
    for (int im = 0; im < 4; ++im) {
#pragma unroll
        for (int jn = 0; jn < 8; ++jn) {
            const float* c = acc[im][jn];
            int gm = row0 + wm + im * 16 + er;
            int gn = col0 + wn + jn * 8 + ec;
            if (sizeof(OutT) == 2) {
                __half2 h01 = __floats2half2_rn(c[0], c[1]);
                __half2 h23 = __floats2half2_rn(c[2], c[3]);
                *reinterpret_cast<__half2*>((__half*)C + (size_t)gm * ldc + gn) = h01;
                *reinterpret_cast<__half2*>((__half*)C + (size_t)(gm + 8) * ldc + gn) = h23;
            } else {
                *reinterpret_cast<float2*>((float*)C + (size_t)gm * ldc + gn) =
                    make_float2(c[0], c[1]);
                *reinterpret_cast<float2*>((float*)C + (size_t)(gm + 8) * ldc + gn) =
                    make_float2(c[2], c[3]);
            }
        }
    }
}

// ---------------------------------------------------------------------------
// Host launcher
// ---------------------------------------------------------------------------
extern "C" void kernel_launch(void* const* d_in, const int* in_sizes, int n_in,
                              void* d_out, int out_size) {
    (void)in_sizes; (void)n_in; (void)out_size;
    const float* x   = (const float*)d_in[0];
    const int*   w1c = (const int*)d_in[1];
    const float* w1a = (const float*)d_in[2];
    const int*   w2c = (const int*)d_in[3];
    const float* w2a = (const float*)d_in[4];
    const int*   w3c = (const int*)d_in[5];
    const float* w3a = (const float*)d_in[6];
    float* out = (float*)d_out;

    __half *pw1, *pw2, *pw3, *px, *pg1, *pg3, *ph;
    cudaGetSymbolAddress((void**)&pw1, g_w1);
    cudaGetSymbolAddress((void**)&pw2, g_w2);
    cudaGetSymbolAddress((void**)&pw3, g_w3);
    cudaGetSymbolAddress((void**)&px,  g_x);
    cudaGetSymbolAddress((void**)&pg1, g_g1);
    cudaGetSymbolAddress((void**)&pg3, g_g3);
    cudaGetSymbolAddress((void**)&ph,  g_h);

    cudaFuncSetAttribute(gemm_kernel<__half>,
                         cudaFuncAttributeMaxDynamicSharedMemorySize, SMEM_BYTES);
    cudaFuncSetAttribute(gemm_kernel<float>,
                         cudaFuncAttributeMaxDynamicSharedMemorySize, SMEM_BYTES);

    {   // weight dequant: NF4 codes (one int32 per code) -> fp16
        const int totalW = HID * DIM;          // 45,088,768
        const int blocks = totalW / 8 / 256;   // exact
        dequant_nf4_kernel<<<blocks, 256>>>(w1c, w1a, pw1, totalW, DIM);
        dequant_nf4_kernel<<<blocks, 256>>>(w3c, w3a, pw3, totalW, DIM);
        dequant_nf4_kernel<<<blocks, 256>>>(w2c, w2a, pw2, totalW, HID);
    }
    {   // x: fp32 -> fp16
        const int totalX = MTOK * DIM;
        convert_x_kernel<<<totalX / 8 / 256, 256>>>(x, px, totalX);
    }

    // G1 = x W1^T, G3 = x W3^T   (M=4096, N=11008, K=4096)
    {
        const int TM = MTOK / BM;   // 32
        const int TN = HID / BN;    // 43
        gemm_kernel<__half><<<TM * TN, THREADS, SMEM_BYTES>>>(px, pw1, pg1, TN, DIM, HID);
        gemm_kernel<__half><<<TM * TN, THREADS, SMEM_BYTES>>>(px, pw3, pg3, TN, DIM, HID);
    }

    // H = silu(G1) * G3
    {
        const int totalH = MTOK * HID;
        swiglu_kernel<<<totalH / 8 / 256, 256>>>(pg1, pg3, ph, totalH);
    }

    // out = H W2^T   (M=4096, N=4096, K=11008)
    {
        const int TM = MTOK / BM;   // 32
        const int TN = DIM / BN;    // 16
        gemm_kernel<float><<<TM * TN, THREADS, SMEM_BYTES>>>(ph, pw2, out, TN, HID, DIM);
    }
}

// round 3
// speedup vs baseline: 1.0765x; 1.0765x over previous
#include <cuda_runtime.h>
#include <cuda_fp16.h>
#include <cstdint>
#include <cstddef>

// ---------------------------------------------------------------------------
// Problem constants
// ---------------------------------------------------------------------------
#define DIM   4096
#define HID   11008
#define MTOK  4096          // B*S = 2*2048

static constexpr int BK = 64;          // 64 fp16 = 128 bytes per row (SW128 atom)
static constexpr int THREADS = 256;    // 8 warps
static constexpr int STAGES = 3;

// Fused GEMM1+3 tiles: A 128 rows, B1 128 rows, B3 128 rows per stage
static constexpr int F_BM = 128;
static constexpr int F_BN = 128;                        // per weight matrix
static constexpr int F_STAGE = (F_BM + 2 * F_BN) * 128; // 48 KB
static constexpr int F_SMEM = STAGES * F_STAGE;         // 144 KB

// GEMM2 tiles: 128 x 256
static constexpr int G_BM = 128;
static constexpr int G_BN = 256;
static constexpr int G_STAGE = (G_BM + G_BN) * 128;     // 48 KB
static constexpr int G_SMEM = STAGES * G_STAGE;         // 144 KB

// ---------------------------------------------------------------------------
// NF4 codebook
// ---------------------------------------------------------------------------
__constant__ float c_nf4[16] = {
    -1.0f, -0.6961928009986877f, -0.5250730514526367f, -0.39491748809814453f,
    -0.28444138169288635f, -0.18477343022823334f, -0.09105003625154495f, 0.0f,
    0.07958029955625534f, 0.16093020141124725f, 0.24611230194568634f,
    0.33791524171829224f, 0.44070982933044434f, 0.5626170039176941f,
    0.6989939212799072f, 1.0f};

// ---------------------------------------------------------------------------
// Static device scratch
// ---------------------------------------------------------------------------
__device__ __align__(256) __half g_w1[(size_t)HID * DIM];
__device__ __align__(256) __half g_w3[(size_t)HID * DIM];
__device__ __align__(256) __half g_w2[(size_t)DIM * HID];
__device__ __align__(256) __half g_x [(size_t)MTOK * DIM];
__device__ __align__(256) __half g_h [(size_t)MTOK * HID];

// ---------------------------------------------------------------------------
// PTX helpers (sm_100 baseline: cp.async, ldmatrix, mma.sync)
// ---------------------------------------------------------------------------
__device__ __forceinline__ uint32_t smem_u32(const void* p) {
    uint32_t r;
    asm("{ .reg .u64 t; cvta.to.shared.u64 t, %1; cvt.u32.u64 %0, t; }"
        : "=r"(r) : "l"(p));
    return r;
}

__device__ __forceinline__ void cp_async16(uint32_t dst, const void* src) {
    asm volatile("cp.async.cg.shared.global [%0], [%1], 16;" :: "r"(dst), "l"(src));
}
__device__ __forceinline__ void cp_async_commit() {
    asm volatile("cp.async.commit_group;" ::: "memory");
}
template <int N>
__device__ __forceinline__ void cp_async_wait() {
    asm volatile("cp.async.wait_group %0;" :: "n"(N) : "memory");
}

__device__ __forceinline__ void ldsm_x4(uint32_t* r, uint32_t addr) {
    asm volatile("ldmatrix.sync.aligned.m8n8.x4.shared.b16 {%0,%1,%2,%3}, [%4];"
                 : "=r"(r[0]), "=r"(r[1]), "=r"(r[2]), "=r"(r[3]) : "r"(addr));
}

__device__ __forceinline__ void mma16816(float* c, const uint32_t* a, const uint32_t* b) {
    asm volatile(
        "mma.sync.aligned.m16n8k16.row.col.f32.f16.f16.f32 "
        "{%0,%1,%2,%3}, {%4,%5,%6,%7}, {%8,%9}, {%0,%1,%2,%3};"
        : "+f"(c[0]), "+f"(c[1]), "+f"(c[2]), "+f"(c[3])
        : "r"(a[0]), "r"(a[1]), "r"(a[2]), "r"(a[3]), "r"(b[0]), "r"(b[1]));
}

__device__ __forceinline__ uint32_t sw128(uint32_t off) {
    return off ^ ((off >> 3) & 0x70);
}

// Load a ROWS x 64(fp16) K-major tile into SW128-swizzled SMEM via cp.async.
template <int ROWS>
__device__ __forceinline__ void load_tile(const __half* __restrict__ g, int ldg,
                                          int row0, int k0, uint32_t sbase, int tid) {
    constexpr int CHUNKS = ROWS * 8;          // 16B chunks
    constexpr int ITER = CHUNKS / THREADS;
#pragma unroll
    for (int i = 0; i < ITER; ++i) {
        int c = tid + i * THREADS;
        int r = c >> 3, cc = c & 7;
        const __half* src = g + (size_t)(row0 + r) * ldg + k0 + cc * 8;
        cp_async16(sbase + sw128((uint32_t)(r * 128 + cc * 16)), src);
    }
}

// ---------------------------------------------------------------------------
// Dequant / convert kernels
// ---------------------------------------------------------------------------
__global__ void __launch_bounds__(256)
dequant_nf4_kernel(const int* __restrict__ codes, const float* __restrict__ absmax,
                   __half* __restrict__ out, int total, int K) {
    int t = blockIdx.x * 256 + threadIdx.x;
    int base = t * 8;
    if (base >= total) return;
    int4 c0 = *reinterpret_cast<const int4*>(codes + base);
    int4 c1 = *reinterpret_cast<const int4*>(codes + base + 4);
    int row = base / K;
    int col = base - row * K;
    float am = absmax[row * (K >> 6) + (col >> 6)];
    __half2 hs[4];
    hs[0] = __floats2half2_rn(c_nf4[c0.x] * am, c_nf4[c0.y] * am);
    hs[1] = __floats2half2_rn(c_nf4[c0.z] * am, c_nf4[c0.w] * am);
    hs[2] = __floats2half2_rn(c_nf4[c1.x] * am, c_nf4[c1.y] * am);
    hs[3] = __floats2half2_rn(c_nf4[c1.z] * am, c_nf4[c1.w] * am);
    *reinterpret_cast<uint4*>(out + base) = *reinterpret_cast<const uint4*>(hs);
}

__global__ void __launch_bounds__(256)
convert_x_kernel(const float* __restrict__ x, __half* __restrict__ out, int total) {
    int t = blockIdx.x * 256 + threadIdx.x;
    int base = t * 8;
    if (base >= total) return;
    float4 a = reinterpret_cast<const float4*>(x + base)[0];
    float4 b = reinterpret_cast<const float4*>(x + base)[1];
    __half2 hs[4];
    hs[0] = __floats2half2_rn(a.x, a.y);
    hs[1] = __floats2half2_rn(a.z, a.w);
    hs[2] = __floats2half2_rn(b.x, b.y);
    hs[3] = __floats2half2_rn(b.z, b.w);
    *reinterpret_cast<uint4*>(out + base) = *reinterpret_cast<const uint4*>(hs);
}

// ---------------------------------------------------------------------------
// Fused GEMM1+GEMM3+SwiGLU:
//   H[m, n] = silu(x @ W1^T) * (x @ W3^T),  fp16 out
// CTA tile: 128(m) x 128(n) per weight, BK=64. 8 warps, warp grid 2(m) x 4(n),
// warp tile 64x32 per weight. A ldmatrix fragments shared between W1 and W3.
// ---------------------------------------------------------------------------
__global__ void __launch_bounds__(THREADS)
fused_gemm13_kernel(const __half* __restrict__ A, const __half* __restrict__ B1,
                    const __half* __restrict__ B3, __half* __restrict__ H) {
    extern __shared__ char smem[];
    const int tid = threadIdx.x;
    const int wid = tid >> 5, lane = tid & 31;
    const uint32_t sb = smem_u32(smem);

    // grouped raster: groups of G m-tiles sweep all n-tiles
    const int TN = HID / F_BN;   // 86
    const int G = 8;
    const int bid = blockIdx.x;
    const int group = bid / (G * TN);
    const int rem = bid - group * (G * TN);
    const int bm = group * G + (rem % G);
    const int bn = rem / G;
    const int row0 = bm * F_BM, col0 = bn * F_BN;

    const int wm = (wid & 1) * 64;       // warp m offset
    const int wn = (wid >> 1) * 32;      // warp n offset (per weight matrix)

    uint32_t sA[STAGES], sB1[STAGES], sB3[STAGES];
#pragma unroll
    for (int s = 0; s < STAGES; ++s) {
        sA[s]  = sb + s * F_STAGE;
        sB1[s] = sA[s] + F_BM * 128;
        sB3[s] = sB1[s] + F_BN * 128;
    }

    const int KT = DIM / BK;    // 64

#pragma unroll
    for (int s = 0; s < STAGES - 1; ++s) {
        load_tile<F_BM>(A,  DIM, row0, s * BK, sA[s], tid);
        load_tile<F_BN>(B1, DIM, col0, s * BK, sB1[s], tid);
        load_tile<F_BN>(B3, DIM, col0, s * BK, sB3[s], tid);
        cp_async_commit();
    }

    float acc1[4][4][4], acc3[4][4][4];
#pragma unroll
    for (int i = 0; i < 4; ++i)
#pragma unroll
        for (int j = 0; j < 4; ++j)
#pragma unroll
            for (int q = 0; q < 4; ++q) { acc1[i][j][q] = 0.f; acc3[i][j][q] = 0.f; }

    const int a_row = wm + ((lane >> 3) & 1) * 8 + (lane & 7);
    const int a_kb  = ((lane >> 4) & 1) * 16;
    const int b_row = wn + ((lane >> 4) & 1) * 8 + (lane & 7);
    const int b_kb  = ((lane >> 3) & 1) * 16;

    for (int kt = 0; kt < KT; ++kt) {
        const int kp = kt + STAGES - 1;
        if (kp < KT) {
            const int sbuf = kp % STAGES;
            load_tile<F_BM>(A,  DIM, row0, kp * BK, sA[sbuf], tid);
            load_tile<F_BN>(B1, DIM, col0, kp * BK, sB1[sbuf], tid);
            load_tile<F_BN>(B3, DIM, col0, kp * BK, sB3[sbuf], tid);
        }
        cp_async_commit();
        cp_async_wait<STAGES - 1>();
        __syncthreads();

        const uint32_t aA  = sA[kt % STAGES];
        const uint32_t aB1 = sB1[kt % STAGES];
        const uint32_t aB3 = sB3[kt % STAGES];
#pragma unroll
        for (int ks = 0; ks < 4; ++ks) {
            uint32_t af[4][4], b1f[2][4], b3f[2][4];
#pragma unroll
            for (int im = 0; im < 4; ++im) {
                uint32_t off = (uint32_t)((a_row + im * 16) * 128 + ks * 32 + a_kb);
                ldsm_x4(af[im], aA + sw128(off));
            }
#pragma unroll
            for (int j16 = 0; j16 < 2; ++j16) {
                uint32_t off = (uint32_t)((b_row + j16 * 16) * 128 + ks * 32 + b_kb);
                ldsm_x4(b1f[j16], aB1 + sw128(off));
                ldsm_x4(b3f[j16], aB3 + sw128(off));
            }
#pragma unroll
            for (int im = 0; im < 4; ++im)
#pragma unroll
                for (int j16 = 0; j16 < 2; ++j16) {
                    mma16816(acc1[im][2 * j16],     af[im], &b1f[j16][0]);
                    mma16816(acc1[im][2 * j16 + 1], af[im], &b1f[j16][2]);
                    mma16816(acc3[im][2 * j16],     af[im], &b3f[j16][0]);
                    mma16816(acc3[im][2 * j16 + 1], af[im], &b3f[j16][2]);
                }
        }
        __syncthreads();
    }

    // epilogue: h = silu(g1) * g3, fp16
    const int er = lane >> 2;
    const int ec = (lane & 3) * 2;
#pragma unroll
    for (int im = 0; im < 4; ++im) {
#pragma unroll
        for (int jn = 0; jn < 4; ++jn) {
            const float* c1 = acc1[im][jn];
            const float* c3 = acc3[im][jn];
            int gm = row0 + wm + im * 16 + er;
            int gn = col0 + wn + jn * 8 + ec;
            float h0 = (c1[0] / (1.f + __expf(-c1[0]))) * c3[0];
            float h1 = (c1[1] / (1.f + __expf(-c1[1]))) * c3[1];
            float h2 = (c1[2] / (1.f + __expf(-c1[2]))) * c3[2];
            float h3 = (c1[3] / (1.f + __expf(-c1[3]))) * c3[3];
            *reinterpret_cast<__half2*>(H + (size_t)gm * HID + gn) =
                __floats2half2_rn(h0, h1);
            *reinterpret_cast<__half2*>(H + (size_t)(gm + 8) * HID + gn) =
                __floats2half2_rn(h2, h3);
        }
    }
}

// ---------------------------------------------------------------------------
// GEMM2: out[m, n] = sum_h H[m, h] * W2[n, h]  (fp32 out)
// CTA 128x256x64, 8 warps of 64x64, 3-stage pipeline.
// ---------------------------------------------------------------------------
__global__ void __launch_bounds__(THREADS)
gemm2_kernel(const __half* __restrict__ A, const __half* __restrict__ B,
             float* __restrict__ C) {
    extern __shared__ char smem[];
    const int tid = threadIdx.x;
    const int wid = tid >> 5, lane = tid & 31;
    const uint32_t sb = smem_u32(smem);

    const int TN = DIM / G_BN;    // 16
    const int G = 8;
    const int bid = blockIdx.x;
    const int group = bid / (G * TN);
    const int rem = bid - group * (G * TN);
    const int bm = group * G + (rem % G);
    const int bn = rem / G;
    const int row0 = bm * G_BM, col0 = bn * G_BN;

    const int wm = (wid & 1) * 64;
    const int wn = (wid >> 1) * 64;

    uint32_t sA[STAGES], sB[STAGES];
#pragma unroll
    for (int s = 0; s < STAGES; ++s) {
        sA[s] = sb + s * G_STAGE;
        sB[s] = sA[s] + G_BM * 128;
    }

    const int KT = HID / BK;   // 172

#pragma unroll
    for (int s = 0; s < STAGES - 1; ++s) {
        load_tile<G_BM>(A, HID, row0, s * BK, sA[s], tid);
        load_tile<G_BN>(B, HID, col0, s * BK, sB[s], tid);
        cp_async_commit();
    }

    float acc[4][8][4];
#pragma unroll
    for (int i = 0; i < 4; ++i)
#pragma unroll
        for (int j = 0; j < 8; ++j)
#pragma unroll
            for (int q = 0; q < 4; ++q) acc[i][j][q] = 0.f;

    const int a_row = wm + ((lane >> 3) & 1) * 8 + (lane & 7);
    const int a_kb  = ((lane >> 4) & 1) * 16;
    const int b_row = wn + ((lane >> 4) & 1) * 8 + (lane & 7);
    const int b_kb  = ((lane >> 3) & 1) * 16;

    for (int kt = 0; kt < KT; ++kt) {
        const int kp = kt + STAGES - 1;
        if (kp < KT) {
            const int sbuf = kp % STAGES;
            load_tile<G_BM>(A, HID, row0, kp * BK, sA[sbuf], tid);
            load_tile<G_BN>(B, HID, col0, kp * BK, sB[sbuf], tid);
        }
        cp_async_commit();
        cp_async_wait<STAGES - 1>();
        __syncthreads();

        const uint32_t aA = sA[kt % STAGES];
        const uint32_t aB = sB[kt % STAGES];
#pragma unroll
        for (int ks = 0; ks < 4; ++ks) {
            uint32_t af[4][4], bf[4][4];
#pragma unroll
            for (int im = 0; im < 4; ++im) {
                uint32_t off = (uint32_t)((a_row + im * 16) * 128 + ks * 32 + a_kb);
                ldsm_x4(af[im], aA + sw128(off));
            }
#pragma unroll
            for (int j16 = 0; j16 < 4; ++j16) {
                uint32_t off = (uint32_t)((b_row + j16 * 16) * 128 + ks * 32 + b_kb);
                ldsm_x4(bf[j16], aB + sw128(off));
            }
#pragma unroll
            for (int im = 0; im < 4; ++im)
#pragma unroll
                for (int j16 = 0; j16 < 4; ++j16) {
                    mma16816(acc[im][2 * j16],     af[im], &bf[j16][0]);
                    mma16816(acc[im][2 * j16 + 1], af[im], &bf[j16][2]);
                }
        }
        __syncthreads();
    }

    const int er = lane >> 2;
    const int ec = (lane & 3) * 2;
#pragma unroll
    for (int im = 0; im < 4; ++im) {
#pragma unroll
        for (int jn = 0; jn < 8; ++jn) {
            const float* c = acc[im][jn];
            int gm = row0 + wm + im * 16 + er;
            int gn = col0 + wn + jn * 8 + ec;
            *reinterpret_cast<float2*>(C + (size_t)gm * DIM + gn) =
                make_float2(c[0], c[1]);
            *reinterpret_cast<float2*>(C + (size_t)(gm + 8) * DIM + gn) =
                make_float2(c[2], c[3]);
        }
    }
}

// ---------------------------------------------------------------------------
// Host launcher
// ---------------------------------------------------------------------------
extern "C" void kernel_launch(void* const* d_in, const int* in_sizes, int n_in,
                              void* d_out, int out_size) {
    (void)in_sizes; (void)n_in; (void)out_size;
    const float* x   = (const float*)d_in[0];
    const int*   w1c = (const int*)d_in[1];
    const float* w1a = (const float*)d_in[2];
    const int*   w2c = (const int*)d_in[3];
    const float* w2a = (const float*)d_in[4];
    const int*   w3c = (const int*)d_in[5];
    const float* w3a = (const float*)d_in[6];
    float* out = (float*)d_out;

    __half *pw1, *pw2, *pw3, *px, *ph;
    cudaGetSymbolAddress((void**)&pw1, g_w1);
    cudaGetSymbolAddress((void**)&pw2, g_w2);
    cudaGetSymbolAddress((void**)&pw3, g_w3);
    cudaGetSymbolAddress((void**)&px,  g_x);
    cudaGetSymbolAddress((void**)&ph,  g_h);

    cudaFuncSetAttribute(fused_gemm13_kernel,
                         cudaFuncAttributeMaxDynamicSharedMemorySize, F_SMEM);
    cudaFuncSetAttribute(gemm2_kernel,
                         cudaFuncAttributeMaxDynamicSharedMemorySize, G_SMEM);

    {   // weight dequant: NF4 codes (one int32 per code) -> fp16
        const int totalW = HID * DIM;          // 45,088,768
        const int blocks = totalW / 8 / 256;
        dequant_nf4_kernel<<<blocks, 256>>>(w1c, w1a, pw1, totalW, DIM);
        dequant_nf4_kernel<<<blocks, 256>>>(w3c, w3a, pw3, totalW, DIM);
        dequant_nf4_kernel<<<blocks, 256>>>(w2c, w2a, pw2, totalW, HID);
    }
    {   // x: fp32 -> fp16
        const int totalX = MTOK * DIM;
        convert_x_kernel<<<totalX / 8 / 256, 256>>>(x, px, totalX);
    }

    // H = silu(x W1^T) * (x W3^T)  — fused, one pass over x
    {
        const int TM = MTOK / F_BM;   // 32
        const int TN = HID / F_BN;    // 86
        fused_gemm13_kernel<<<TM * TN, THREADS, F_SMEM>>>(px, pw1, pw3, ph);
    }

    // out = H W2^T
    {
        const int TM = MTOK / G_BM;   // 32
        const int TN = DIM / G_BN;    // 16
        gemm2_kernel<<<TM * TN, THREADS, G_SMEM>>>(ph, pw2, out);
    }
}

// round 4
// speedup vs baseline: 1.2316x; 1.1442x over previous
#include <cuda_runtime.h>
#include <cuda_fp16.h>
#include <cstdint>
#include <cstddef>

// ---------------------------------------------------------------------------
// Problem constants
// ---------------------------------------------------------------------------
#define DIM   4096
#define HID   11008
#define MTOK  4096          // B*S = 2*2048

static constexpr int BK = 64;          // 64 fp16 = 128 bytes per row (SW128 atom)
static constexpr int THREADS = 256;    // 8 warps
static constexpr int STAGES = 3;

// Fused GEMM1+3: CTA 128(m) x 64(n per matrix); stage = A 16K + B1 8K + B3 8K
static constexpr int F_BM = 128;
static constexpr int F_BN = 64;                         // per weight matrix
static constexpr int F_STAGE = (F_BM + 2 * F_BN) * 128; // 32 KB
static constexpr int F_SMEM = STAGES * F_STAGE;         // 96 KB

// GEMM2: CTA 128 x 128
static constexpr int G_BM = 128;
static constexpr int G_BN = 128;
static constexpr int G_STAGE = (G_BM + G_BN) * 128;     // 32 KB
static constexpr int G_SMEM = STAGES * G_STAGE;         // 96 KB

// ---------------------------------------------------------------------------
// NF4 codebook
// ---------------------------------------------------------------------------
__constant__ float c_nf4[16] = {
    -1.0f, -0.6961928009986877f, -0.5250730514526367f, -0.39491748809814453f,
    -0.28444138169288635f, -0.18477343022823334f, -0.09105003625154495f, 0.0f,
    0.07958029955625534f, 0.16093020141124725f, 0.24611230194568634f,
    0.33791524171829224f, 0.44070982933044434f, 0.5626170039176941f,
    0.6989939212799072f, 1.0f};

// ---------------------------------------------------------------------------
// Static device scratch
// ---------------------------------------------------------------------------
__device__ __align__(256) __half g_w1[(size_t)HID * DIM];
__device__ __align__(256) __half g_w3[(size_t)HID * DIM];
__device__ __align__(256) __half g_w2[(size_t)DIM * HID];
__device__ __align__(256) __half g_x [(size_t)MTOK * DIM];
__device__ __align__(256) __half g_h [(size_t)MTOK * HID];

// ---------------------------------------------------------------------------
// PTX helpers (sm_100 baseline: cp.async, ldmatrix, mma.sync)
// ---------------------------------------------------------------------------
__device__ __forceinline__ uint32_t smem_u32(const void* p) {
    uint32_t r;
    asm("{ .reg .u64 t; cvta.to.shared.u64 t, %1; cvt.u32.u64 %0, t; }"
        : "=r"(r) : "l"(p));
    return r;
}

__device__ __forceinline__ void cp_async16(uint32_t dst, const void* src) {
    asm volatile("cp.async.cg.shared.global [%0], [%1], 16;" :: "r"(dst), "l"(src));
}
__device__ __forceinline__ void cp_async_commit() {
    asm volatile("cp.async.commit_group;" ::: "memory");
}
template <int N>
__device__ __forceinline__ void cp_async_wait() {
    asm volatile("cp.async.wait_group %0;" :: "n"(N) : "memory");
}

__device__ __forceinline__ void ldsm_x4(uint32_t* r, uint32_t addr) {
    asm volatile("ldmatrix.sync.aligned.m8n8.x4.shared.b16 {%0,%1,%2,%3}, [%4];"
                 : "=r"(r[0]), "=r"(r[1]), "=r"(r[2]), "=r"(r[3]) : "r"(addr));
}

__device__ __forceinline__ void mma16816(float* c, const uint32_t* a, const uint32_t* b) {
    asm volatile(
        "mma.sync.aligned.m16n8k16.row.col.f32.f16.f16.f32 "
        "{%0,%1,%2,%3}, {%4,%5,%6,%7}, {%8,%9}, {%0,%1,%2,%3};"
        : "+f"(c[0]), "+f"(c[1]), "+f"(c[2]), "+f"(c[3])
        : "r"(a[0]), "r"(a[1]), "r"(a[2]), "r"(a[3]), "r"(b[0]), "r"(b[1]));
}

__device__ __forceinline__ uint32_t sw128(uint32_t off) {
    return off ^ ((off >> 3) & 0x70);
}

// Load a ROWS x 64(fp16) K-major tile into SW128-swizzled SMEM via cp.async.
template <int ROWS>
__device__ __forceinline__ void load_tile(const __half* __restrict__ g, int ldg,
                                          int row0, int k0, uint32_t sbase, int tid) {
    constexpr int CHUNKS = ROWS * 8;          // 16B chunks
    constexpr int ITER = CHUNKS / THREADS;
#pragma unroll
    for (int i = 0; i < ITER; ++i) {
        int c = tid + i * THREADS;
        int r = c >> 3, cc = c & 7;
        const __half* src = g + (size_t)(row0 + r) * ldg + k0 + cc * 8;
        cp_async16(sbase + sw128((uint32_t)(r * 128 + cc * 16)), src);
    }
}

// ---------------------------------------------------------------------------
// Dequant / convert kernels
// ---------------------------------------------------------------------------
__global__ void __launch_bounds__(256)
dequant_nf4_kernel(const int* __restrict__ codes, const float* __restrict__ absmax,
                   __half* __restrict__ out, int total, int K) {
    int t = blockIdx.x * 256 + threadIdx.x;
    int base = t * 8;
    if (base >= total) return;
    int4 c0 = *reinterpret_cast<const int4*>(codes + base);
    int4 c1 = *reinterpret_cast<const int4*>(codes + base + 4);
    int row = base / K;
    int col = base - row * K;
    float am = absmax[row * (K >> 6) + (col >> 6)];
    __half2 hs[4];
    hs[0] = __floats2half2_rn(c_nf4[c0.x] * am, c_nf4[c0.y] * am);
    hs[1] = __floats2half2_rn(c_nf4[c0.z] * am, c_nf4[c0.w] * am);
    hs[2] = __floats2half2_rn(c_nf4[c1.x] * am, c_nf4[c1.y] * am);
    hs[3] = __floats2half2_rn(c_nf4[c1.z] * am, c_nf4[c1.w] * am);
    *reinterpret_cast<uint4*>(out + base) = *reinterpret_cast<const uint4*>(hs);
}

__global__ void __launch_bounds__(256)
convert_x_kernel(const float* __restrict__ x, __half* __restrict__ out, int total) {
    int t = blockIdx.x * 256 + threadIdx.x;
    int base = t * 8;
    if (base >= total) return;
    float4 a = reinterpret_cast<const float4*>(x + base)[0];
    float4 b = reinterpret_cast<const float4*>(x + base)[1];
    __half2 hs[4];
    hs[0] = __floats2half2_rn(a.x, a.y);
    hs[1] = __floats2half2_rn(a.z, a.w);
    hs[2] = __floats2half2_rn(b.x, b.y);
    hs[3] = __floats2half2_rn(b.z, b.w);
    *reinterpret_cast<uint4*>(out + base) = *reinterpret_cast<const uint4*>(hs);
}

// ---------------------------------------------------------------------------
// Fused GEMM1+GEMM3+SwiGLU:  H = silu(x W1^T) * (x W3^T), fp16 out.
// CTA 128m x 64n per matrix; 8 warps (2m x 4n), warp tile 64m x 16n/matrix.
// 3-stage cp.async pipeline, ONE __syncthreads per k-tile, 2 CTAs/SM.
// ---------------------------------------------------------------------------
__global__ void __launch_bounds__(THREADS, 2)
fused_gemm13_kernel(const __half* __restrict__ A, const __half* __restrict__ B1,
                    const __half* __restrict__ B3, __half* __restrict__ H) {
    extern __shared__ char smem[];
    const int tid = threadIdx.x;
    const int wid = tid >> 5, lane = tid & 31;
    const uint32_t sb = smem_u32(smem);

    // grouped raster: groups of G m-tiles sweep all n-tiles
    const int TN = HID / F_BN;   // 172
    const int G = 16;
    const int bid = blockIdx.x;
    const int group = bid / (G * TN);
    const int rem = bid - group * (G * TN);
    const int bm = group * G + (rem % G);
    const int bn = rem / G;
    const int row0 = bm * F_BM, col0 = bn * F_BN;

    const int wm = (wid & 1) * 64;       // warp m offset
    const int wn = (wid >> 1) * 16;      // warp n offset (per weight matrix)

    uint32_t sA[STAGES], sB1[STAGES], sB3[STAGES];
#pragma unroll
    for (int s = 0; s < STAGES; ++s) {
        sA[s]  = sb + s * F_STAGE;
        sB1[s] = sA[s] + F_BM * 128;
        sB3[s] = sB1[s] + F_BN * 128;
    }

    const int KT = DIM / BK;    // 64

#pragma unroll
    for (int s = 0; s < STAGES - 1; ++s) {
        load_tile<F_BM>(A,  DIM, row0, s * BK, sA[s], tid);
        load_tile<F_BN>(B1, DIM, col0, s * BK, sB1[s], tid);
        load_tile<F_BN>(B3, DIM, col0, s * BK, sB3[s], tid);
        cp_async_commit();
    }

    float acc1[4][2][4], acc3[4][2][4];
#pragma unroll
    for (int i = 0; i < 4; ++i)
#pragma unroll
        for (int j = 0; j < 2; ++j)
#pragma unroll
            for (int q = 0; q < 4; ++q) { acc1[i][j][q] = 0.f; acc3[i][j][q] = 0.f; }

    const int a_row = wm + ((lane >> 3) & 1) * 8 + (lane & 7);
    const int a_kb  = ((lane >> 4) & 1) * 16;
    const int b_row = wn + ((lane >> 4) & 1) * 8 + (lane & 7);
    const int b_kb  = ((lane >> 3) & 1) * 16;

    for (int kt = 0; kt < KT; ++kt) {
        cp_async_wait<STAGES - 2>();   // stage kt%S ready
        __syncthreads();               // all warps done computing kt-1
        const int kp = kt + STAGES - 1;
        if (kp < KT) {                 // prefetch into just-freed stage (kt-1)%S
            const int sbuf = kp % STAGES;
            load_tile<F_BM>(A,  DIM, row0, kp * BK, sA[sbuf], tid);
            load_tile<F_BN>(B1, DIM, col0, kp * BK, sB1[sbuf], tid);
            load_tile<F_BN>(B3, DIM, col0, kp * BK, sB3[sbuf], tid);
        }
        cp_async_commit();

        const uint32_t aA  = sA[kt % STAGES];
        const uint32_t aB1 = sB1[kt % STAGES];
        const uint32_t aB3 = sB3[kt % STAGES];
#pragma unroll
        for (int ks = 0; ks < 4; ++ks) {
            uint32_t af[4][4], b1f[4], b3f[4];
            uint32_t boff = (uint32_t)(b_row * 128 + ks * 32 + b_kb);
            ldsm_x4(b1f, aB1 + sw128(boff));
            ldsm_x4(b3f, aB3 + sw128(boff));
#pragma unroll
            for (int im = 0; im < 4; ++im) {
                uint32_t off = (uint32_t)((a_row + im * 16) * 128 + ks * 32 + a_kb);
                ldsm_x4(af[im], aA + sw128(off));
            }
#pragma unroll
            for (int im = 0; im < 4; ++im) {
                mma16816(acc1[im][0], af[im], &b1f[0]);
                mma16816(acc1[im][1], af[im], &b1f[2]);
                mma16816(acc3[im][0], af[im], &b3f[0]);
                mma16816(acc3[im][1], af[im], &b3f[2]);
            }
        }
    }
    cp_async_wait<0>();

    // epilogue: h = silu(g1) * g3, fp16
    const int er = lane >> 2;
    const int ec = (lane & 3) * 2;
#pragma unroll
    for (int im = 0; im < 4; ++im) {
#pragma unroll
        for (int jn = 0; jn < 2; ++jn) {
            const float* c1 = acc1[im][jn];
            const float* c3 = acc3[im][jn];
            int gm = row0 + wm + im * 16 + er;
            int gn = col0 + wn + jn * 8 + ec;
            float h0 = (c1[0] / (1.f + __expf(-c1[0]))) * c3[0];
            float h1 = (c1[1] / (1.f + __expf(-c1[1]))) * c3[1];
            float h2 = (c1[2] / (1.f + __expf(-c1[2]))) * c3[2];
            float h3 = (c1[3] / (1.f + __expf(-c1[3]))) * c3[3];
            *reinterpret_cast<__half2*>(H + (size_t)gm * HID + gn) =
                __floats2half2_rn(h0, h1);
            *reinterpret_cast<__half2*>(H + (size_t)(gm + 8) * HID + gn) =
                __floats2half2_rn(h2, h3);
        }
    }
}

// ---------------------------------------------------------------------------
// GEMM2: out[m, n] = sum_h H[m, h] * W2[n, h]  (fp32 out)
// CTA 128x128x64; 8 warps (2m x 4n), warp tile 64x32. 2 CTAs/SM.
// ---------------------------------------------------------------------------
__global__ void __launch_bounds__(THREADS, 2)
gemm2_kernel(const __half* __restrict__ A, const __half* __restrict__ B,
             float* __restrict__ C) {
    extern __shared__ char smem[];
    const int tid = threadIdx.x;
    const int wid = tid >> 5, lane = tid & 31;
    const uint32_t sb = smem_u32(smem);

    const int TN = DIM / G_BN;    // 32
    const int G = 16;
    const int bid = blockIdx.x;
    const int group = bid / (G * TN);
    const int rem = bid - group * (G * TN);
    const int bm = group * G + (rem % G);
    const int bn = rem / G;
    const int row0 = bm * G_BM, col0 = bn * G_BN;

    const int wm = (wid & 1) * 64;
    const int wn = (wid >> 1) * 32;

    uint32_t sA[STAGES], sB[STAGES];
#pragma unroll
    for (int s = 0; s < STAGES; ++s) {
        sA[s] = sb + s * G_STAGE;
        sB[s] = sA[s] + G_BM * 128;
    }

    const int KT = HID / BK;   // 172

#pragma unroll
    for (int s = 0; s < STAGES - 1; ++s) {
        load_tile<G_BM>(A, HID, row0, s * BK, sA[s], tid);
        load_tile<G_BN>(B, HID, col0, s * BK, sB[s], tid);
        cp_async_commit();
    }

    float acc[4][4][4];
#pragma unroll
    for (int i = 0; i < 4; ++i)
#pragma unroll
        for (int j = 0; j < 4; ++j)
#pragma unroll
            for (int q = 0; q < 4; ++q) acc[i][j][q] = 0.f;

    const int a_row = wm + ((lane >> 3) & 1) * 8 + (lane & 7);
    const int a_kb  = ((lane >> 4) & 1) * 16;
    const int b_row = wn + ((lane >> 4) & 1) * 8 + (lane & 7);
    const int b_kb  = ((lane >> 3) & 1) * 16;

    for (int kt = 0; kt < KT; ++kt) {
        cp_async_wait<STAGES - 2>();
        __syncthreads();
        const int kp = kt + STAGES - 1;
        if (kp < KT) {
            const int sbuf = kp % STAGES;
            load_tile<G_BM>(A, HID, row0, kp * BK, sA[sbuf], tid);
            load_tile<G_BN>(B, HID, col0, kp * BK, sB[sbuf], tid);
        }
        cp_async_commit();

        const uint32_t aA = sA[kt % STAGES];
        const uint32_t aB = sB[kt % STAGES];
#pragma unroll
        for (int ks = 0; ks < 4; ++ks) {
            uint32_t af[4][4], bf[2][4];
#pragma unroll
            for (int j16 = 0; j16 < 2; ++j16) {
                uint32_t off = (uint32_t)((b_row + j16 * 16) * 128 + ks * 32 + b_kb);
                ldsm_x4(bf[j16], aB + sw128(off));
            }
#pragma unroll
            for (int im = 0; im < 4; ++im) {
                uint32_t off = (uint32_t)((a_row + im * 16) * 128 + ks * 32 + a_kb);
                ldsm_x4(af[im], aA + sw128(off));
            }
#pragma unroll
            for (int im = 0; im < 4; ++im)
#pragma unroll
                for (int j16 = 0; j16 < 2; ++j16) {
                    mma16816(acc[im][2 * j16],     af[im], &bf[j16][0]);
                    mma16816(acc[im][2 * j16 + 1], af[im], &bf[j16][2]);
                }
        }
    }
    cp_async_wait<0>();

    const int er = lane >> 2;
    const int ec = (lane & 3) * 2;
#pragma unroll
    for (int im = 0; im < 4; ++im) {
#pragma unroll
        for (int jn = 0; jn < 4; ++jn) {
            const float* c = acc[im][jn];
            int gm = row0 + wm + im * 16 + er;
            int gn = col0 + wn + jn * 8 + ec;
            *reinterpret_cast<float2*>(C + (size_t)gm * DIM + gn) =
                make_float2(c[0], c[1]);
            *reinterpret_cast<float2*>(C + (size_t)(gm + 8) * DIM + gn) =
                make_float2(c[2], c[3]);
        }
    }
}

// ---------------------------------------------------------------------------
// Host launcher
// ---------------------------------------------------------------------------
extern "C" void kernel_launch(void* const* d_in, const int* in_sizes, int n_in,
                              void* d_out, int out_size) {
    (void)in_sizes; (void)n_in; (void)out_size;
    const float* x   = (const float*)d_in[0];
    const int*   w1c = (const int*)d_in[1];
    const float* w1a = (const float*)d_in[2];
    const int*   w2c = (const int*)d_in[3];
    const float* w2a = (const float*)d_in[4];
    const int*   w3c = (const int*)d_in[5];
    const float* w3a = (const float*)d_in[6];
    float* out = (float*)d_out;

    __half *pw1, *pw2, *pw3, *px, *ph;
    cudaGetSymbolAddress((void**)&pw1, g_w1);
    cudaGetSymbolAddress((void**)&pw2, g_w2);
    cudaGetSymbolAddress((void**)&pw3, g_w3);
    cudaGetSymbolAddress((void**)&px,  g_x);
    cudaGetSymbolAddress((void**)&ph,  g_h);

    cudaFuncSetAttribute(fused_gemm13_kernel,
                         cudaFuncAttributeMaxDynamicSharedMemorySize, F_SMEM);
    cudaFuncSetAttribute(gemm2_kernel,
                         cudaFuncAttributeMaxDynamicSharedMemorySize, G_SMEM);

    {   // weight dequant: NF4 codes (one int32 per code) -> fp16
        const int totalW = HID * DIM;          // 45,088,768
        const int blocks = totalW / 8 / 256;
        dequant_nf4_kernel<<<blocks, 256>>>(w1c, w1a, pw1, totalW, DIM);
        dequant_nf4_kernel<<<blocks, 256>>>(w3c, w3a, pw3, totalW, DIM);
        dequant_nf4_kernel<<<blocks, 256>>>(w2c, w2a, pw2, totalW, HID);
    }
    {   // x: fp32 -> fp16
        const int totalX = MTOK * DIM;
        convert_x_kernel<<<totalX / 8 / 256, 256>>>(x, px, totalX);
    }

    // H = silu(x W1^T) * (x W3^T)  — fused, one pass over x
    {
        const int TM = MTOK / F_BM;   // 32
        const int TN = HID / F_BN;    // 172
        fused_gemm13_kernel<<<TM * TN, THREADS, F_SMEM>>>(px, pw1, pw3, ph);
    }

    // out = H W2^T
    {
        const int TM = MTOK / G_BM;   // 32
        const int TN = DIM / G_BN;    // 32
        gemm2_kernel<<<TM * TN, THREADS, G_SMEM>>>(ph, pw2, out);
    }
}